// round 1
// baseline (speedup 1.0000x reference)
#include <cuda_runtime.h>

// TripletLoss: N=384 points, D=128, 16 classes, margin=0.3
// Plan:
//   memsetAsync  : zero out[0..1]
//   dist_kernel  : dist[i][j] = sq_i + sq_j - 2*dot(e_i,e_j)  (fp32, smem-tiled)
//   triplet_kernel: per-anchor block; compact positives; each thread = one
//                   negative; accumulate L in (0, margin); block-reduce + atomics.

#define MARGIN_F 0.3f
constexpr int NPTS = 384;
constexpr int DIM  = 128;

__device__ float g_dist[NPTS * NPTS];

// grid (12,12), block (16,16). Each block computes a 32x32 tile of dist.
// Each thread computes a 2x2 register tile (strided by 16).
__global__ __launch_bounds__(256) void dist_kernel(const float* __restrict__ E) {
    __shared__ float As[32][132];   // 132 pad: float4-aligned, reduces LDS conflicts
    __shared__ float Bs[32][132];
    __shared__ float sqA[32];
    __shared__ float sqB[32];

    const int tx  = threadIdx.x;           // 0..15
    const int ty  = threadIdx.y;           // 0..15
    const int tid = ty * 16 + tx;
    const int i0  = blockIdx.y * 32;
    const int j0  = blockIdx.x * 32;

    // Load 32x128 A-tile and B-tile (1024 float4 each), coalesced.
    const float4* E4 = reinterpret_cast<const float4*>(E);
    #pragma unroll
    for (int idx = tid; idx < 1024; idx += 256) {
        int r = idx >> 5;       // row within tile (0..31)
        int c = idx & 31;       // float4 column (0..31)
        float4 a = E4[(i0 + r) * (DIM / 4) + c];
        float4 b = E4[(j0 + r) * (DIM / 4) + c];
        *reinterpret_cast<float4*>(&As[r][c * 4]) = a;
        *reinterpret_cast<float4*>(&Bs[r][c * 4]) = b;
    }
    __syncthreads();

    // Squared norms for the 32 A-rows (warp 0) and 32 B-rows (warp 1).
    if (tid < 64) {
        int r = tid & 31;
        const float* row = (tid < 32) ? &As[r][0] : &Bs[r][0];
        float s = 0.f;
        #pragma unroll
        for (int k = 0; k < DIM; k++) s += row[k] * row[k];
        if (tid < 32) sqA[r] = s; else sqB[r] = s;
    }
    __syncthreads();

    float a00 = 0.f, a01 = 0.f, a10 = 0.f, a11 = 0.f;
    const int r0 = ty, r1 = ty + 16, c0 = tx, c1 = tx + 16;
    #pragma unroll
    for (int k = 0; k < DIM; k += 4) {
        float4 va0 = *reinterpret_cast<const float4*>(&As[r0][k]);
        float4 va1 = *reinterpret_cast<const float4*>(&As[r1][k]);
        float4 vb0 = *reinterpret_cast<const float4*>(&Bs[c0][k]);
        float4 vb1 = *reinterpret_cast<const float4*>(&Bs[c1][k]);
        a00 += va0.x * vb0.x + va0.y * vb0.y + va0.z * vb0.z + va0.w * vb0.w;
        a01 += va0.x * vb1.x + va0.y * vb1.y + va0.z * vb1.z + va0.w * vb1.w;
        a10 += va1.x * vb0.x + va1.y * vb0.y + va1.z * vb0.z + va1.w * vb0.w;
        a11 += va1.x * vb1.x + va1.y * vb1.y + va1.z * vb1.z + va1.w * vb1.w;
    }

    // dist = (sq_i + sq_j) - 2*dot  (matches reference op ordering)
    g_dist[(i0 + r0) * NPTS + (j0 + c0)] = (sqA[r0] + sqB[c0]) - 2.0f * a00;
    g_dist[(i0 + r0) * NPTS + (j0 + c1)] = (sqA[r0] + sqB[c1]) - 2.0f * a01;
    g_dist[(i0 + r1) * NPTS + (j0 + c0)] = (sqA[r1] + sqB[c0]) - 2.0f * a10;
    g_dist[(i0 + r1) * NPTS + (j0 + c1)] = (sqA[r1] + sqB[c1]) - 2.0f * a11;
}

// grid (384), block (384). Block b = anchor i. Threads parallelize over
// negatives n; inner loop over compacted positives p (same label as i,
// including p==i, matching the reference's kept diagonal).
__global__ __launch_bounds__(NPTS) void triplet_kernel(const int* __restrict__ labels,
                                                       float* __restrict__ out) {
    __shared__ float drow[NPTS];
    __shared__ int   slab[NPTS];
    __shared__ float pdist[NPTS];
    __shared__ int   npos;
    __shared__ float wsum[12];
    __shared__ float wcnt[12];

    const int i = blockIdx.x;
    const int t = threadIdx.x;
    if (t == 0) npos = 0;
    slab[t] = labels[t];
    drow[t] = g_dist[i * NPTS + t];
    __syncthreads();

    const int li = slab[i];
    if (slab[t] == li) {
        int k = atomicAdd(&npos, 1);
        pdist[k] = drow[t];
    }
    __syncthreads();

    float sum = 0.f;
    float cnt = 0.f;
    if (slab[t] != li) {
        const float dn = drow[t];
        const int P = npos;
        for (int p = 0; p < P; p++) {
            float L = (pdist[p] - dn) + MARGIN_F;
            if (L > 0.f && L < MARGIN_F) { sum += L; cnt += 1.f; }
        }
    }

    // warp reduce (12 warps)
    #pragma unroll
    for (int o = 16; o > 0; o >>= 1) {
        sum += __shfl_down_sync(0xffffffffu, sum, o);
        cnt += __shfl_down_sync(0xffffffffu, cnt, o);
    }
    if ((t & 31) == 0) { wsum[t >> 5] = sum; wcnt[t >> 5] = cnt; }
    __syncthreads();
    if (t == 0) {
        float s = 0.f, c = 0.f;
        #pragma unroll
        for (int w = 0; w < 12; w++) { s += wsum[w]; c += wcnt[w]; }
        atomicAdd(&out[0], s);
        atomicAdd(&out[1], c);
    }
}

extern "C" void kernel_launch(void* const* d_in, const int* in_sizes, int n_in,
                              void* d_out, int out_size) {
    const float* E      = (const float*)d_in[0];   // embeddings [384,128] f32
    const int*   labels = (const int*)d_in[1];     // labels [384] i32
    float* out = (float*)d_out;                    // [losses, count] f32

    cudaMemsetAsync(out, 0, (size_t)out_size * sizeof(float));
    dist_kernel<<<dim3(12, 12), dim3(16, 16)>>>(E);
    triplet_kernel<<<NPTS, NPTS>>>(labels, out);
}